// round 11
// baseline (speedup 1.0000x reference)
#include <cuda_runtime.h>
#include <cuda_bf16.h>

#define N_NODES 100000
#define E_MAX   1600000
#define F 32
#define SCAN_T 1024

__device__ float g_dinv[N_NODES];
__device__ float g_hs[N_NODES * F];
__device__ float g_agg[N_NODES * F];
__device__ float g_gmax[F];
__device__ int   g_cnt[N_NODES];
__device__ int   g_ptr[N_NODES];   // after k_fill: END of each node's segment
__device__ int   g_csr[E_MAX];     // src node per dst-grouped edge

// ---------------- zero counts + pool accumulator ----------------
__global__ void k_zero(int n) {
    int i = blockIdx.x * blockDim.x + threadIdx.x;
    if (i < n) g_cnt[i] = 0;
    if (i < F) g_gmax[i] = 0.f;
}

// ---------------- count edges per dst ----------------
__global__ void k_count(const int* __restrict__ dst, int E) {
    int e = blockIdx.x * blockDim.x + threadIdx.x;
    if (e < E) atomicAdd(&g_cnt[__ldg(&dst[e])], 1);
}

// ---------------- exclusive scan of counts (single block) ----------------
__global__ void k_scan(int n) {
    __shared__ int part[SCAN_T];
    int t = threadIdx.x;
    int per = (n + SCAN_T - 1) / SCAN_T;
    int b = t * per;
    int e = min(b + per, n);
    int s = 0;
    for (int i = b; i < e; i++) s += g_cnt[i];
    part[t] = s;
    __syncthreads();
    // Hillis-Steele inclusive scan
    for (int o = 1; o < SCAN_T; o <<= 1) {
        int v = (t >= o) ? part[t - o] : 0;
        __syncthreads();
        part[t] += v;
        __syncthreads();
    }
    int run = part[t] - s;   // exclusive offset for this thread's range
    for (int i = b; i < e; i++) { g_ptr[i] = run; run += g_cnt[i]; }
}

// ---------------- fill CSR (g_ptr advances to segment end) ----------------
__global__ void k_fill(const int* __restrict__ src, const int* __restrict__ dst, int E) {
    int e = blockIdx.x * blockDim.x + threadIdx.x;
    if (e >= E) return;
    int d = __ldg(&dst[e]);
    int pos = atomicAdd(&g_ptr[d], 1);
    g_csr[pos] = __ldg(&src[e]);
}

// ---------------- layer 1: dinv, hs = (x@W1)*dinv ----------------
__global__ void k_h1(const float* __restrict__ x, const float* __restrict__ W1, int n) {
    __shared__ float sW[8 * F];
    int t = threadIdx.x;
    if (t < 8 * F) sW[t] = W1[t];
    __syncthreads();
    int i = blockIdx.x * blockDim.x + t;
    if (i >= n) return;
    float di = rsqrtf((float)g_cnt[i] + 1.0f);  // +1 self loop
    g_dinv[i] = di;

    float4 a0 = *(const float4*)(x + i * 8);
    float4 a1 = *(const float4*)(x + i * 8 + 4);
    float xv[8] = {a0.x, a0.y, a0.z, a0.w, a1.x, a1.y, a1.z, a1.w};

    float h[F];
#pragma unroll
    for (int j = 0; j < F; j++) h[j] = 0.f;
#pragma unroll
    for (int k = 0; k < 8; k++) {
        float xk = xv[k];
#pragma unroll
        for (int j = 0; j < F; j++) h[j] = fmaf(xk, sW[k * F + j], h[j]);
    }
    float4* hp = (float4*)(g_hs + i * F);
#pragma unroll
    for (int q = 0; q < F / 4; q++)
        hp[q] = make_float4(h[q*4+0]*di, h[q*4+1]*di, h[q*4+2]*di, h[q*4+3]*di);
}

// ---------------- gather: agg[i] = hs[i] + sum_{s in N(i)} hs[s] ----------------
// one warp per node; 4 edges x 8 lanes (float4 chunk each) per iteration
__global__ void k_gather(int n) {
    unsigned int gt = blockIdx.x * blockDim.x + threadIdx.x;
    unsigned int w = gt >> 5;          // node
    if (w >= (unsigned int)n) return;
    int lane = threadIdx.x & 31;
    int sub  = lane >> 3;              // edge slot 0..3
    int q    = (lane & 7) << 2;        // feature chunk offset

    int end = g_ptr[w];                // segment end (g_ptr advanced by k_fill)
    int cnt = g_cnt[w];
    int beg = end - cnt;

    float4 acc = make_float4(0.f, 0.f, 0.f, 0.f);
    for (int p = beg + sub; p < end; p += 4) {
        int s = __ldg(&g_csr[p]);
        const float4 v = *(const float4*)(g_hs + s * F + q);
        acc.x += v.x; acc.y += v.y; acc.z += v.z; acc.w += v.w;
    }
    // reduce the 4 edge-slot groups down to lanes 0..7
#pragma unroll
    for (int o = 16; o >= 8; o >>= 1) {
        acc.x += __shfl_down_sync(0xFFFFFFFFu, acc.x, o);
        acc.y += __shfl_down_sync(0xFFFFFFFFu, acc.y, o);
        acc.z += __shfl_down_sync(0xFFFFFFFFu, acc.z, o);
        acc.w += __shfl_down_sync(0xFFFFFFFFu, acc.w, o);
    }
    if (sub == 0) {
        const float4 self = *(const float4*)(g_hs + w * F + q);
        *(float4*)(g_agg + w * F + q) =
            make_float4(acc.x + self.x, acc.y + self.y, acc.z + self.z, acc.w + self.w);
    }
}

// ---------------- layer 2: a = relu(dinv*agg+b1); hs = (a@W2)*dinv ----------------
__global__ void k_h2(const float* __restrict__ W2, const float* __restrict__ b1, int n) {
    __shared__ float sW[F * F];
    __shared__ float sb[F];
    int t = threadIdx.x;
    for (int k = t; k < F * F; k += blockDim.x) sW[k] = W2[k];
    if (t < F) sb[t] = b1[t];
    __syncthreads();
    int i = blockIdx.x * blockDim.x + t;
    if (i >= n) return;
    float di = g_dinv[i];

    float a[F];
    const float4* gp = (const float4*)(g_agg + i * F);
#pragma unroll
    for (int q = 0; q < F / 4; q++) {
        float4 v = gp[q];
        a[q*4+0] = fmaxf(fmaf(di, v.x, sb[q*4+0]), 0.f);
        a[q*4+1] = fmaxf(fmaf(di, v.y, sb[q*4+1]), 0.f);
        a[q*4+2] = fmaxf(fmaf(di, v.z, sb[q*4+2]), 0.f);
        a[q*4+3] = fmaxf(fmaf(di, v.w, sb[q*4+3]), 0.f);
    }
    float h[F];
#pragma unroll
    for (int j = 0; j < F; j++) h[j] = 0.f;
#pragma unroll
    for (int k = 0; k < F; k++) {
        float ak = a[k];
#pragma unroll
        for (int j = 0; j < F; j++) h[j] = fmaf(ak, sW[k * F + j], h[j]);
    }
    float4* hp = (float4*)(g_hs + i * F);
#pragma unroll
    for (int q = 0; q < F / 4; q++)
        hp[q] = make_float4(h[q*4+0]*di, h[q*4+1]*di, h[q*4+2]*di, h[q*4+3]*di);
}

// ---------------- final: relu + global max pool ----------------
__global__ void k_final(const float* __restrict__ b2, int n) {
    __shared__ float sb[F];
    __shared__ int smax[F];
    int t = threadIdx.x;
    if (t < F) { sb[t] = b2[t]; smax[t] = 0; }
    __syncthreads();
    int i = blockIdx.x * blockDim.x + t;

    float v[F];
    if (i < n) {
        float di = g_dinv[i];
        const float4* gp = (const float4*)(g_agg + i * F);
#pragma unroll
        for (int q = 0; q < F / 4; q++) {
            float4 w = gp[q];
            v[q*4+0] = fmaxf(fmaf(di, w.x, sb[q*4+0]), 0.f);
            v[q*4+1] = fmaxf(fmaf(di, w.y, sb[q*4+1]), 0.f);
            v[q*4+2] = fmaxf(fmaf(di, w.z, sb[q*4+2]), 0.f);
            v[q*4+3] = fmaxf(fmaf(di, w.w, sb[q*4+3]), 0.f);
        }
    } else {
#pragma unroll
        for (int j = 0; j < F; j++) v[j] = 0.f;
    }
    // warp-level max per feature (ReLU output >= 0 -> int compare valid)
#pragma unroll
    for (int o = 16; o > 0; o >>= 1) {
#pragma unroll
        for (int j = 0; j < F; j++)
            v[j] = fmaxf(v[j], __shfl_xor_sync(0xFFFFFFFFu, v[j], o));
    }
    if ((t & 31) == 0) {
#pragma unroll
        for (int j = 0; j < F; j++) atomicMax(&smax[j], __float_as_int(v[j]));
    }
    __syncthreads();
    if (t < F) atomicMax((int*)&g_gmax[t], smax[t]);
}

// ---------------- head: g@fcW + fcb, log_softmax ----------------
__global__ void k_head(const float* __restrict__ fcW, const float* __restrict__ fcb,
                       float* __restrict__ out) {
    if (threadIdx.x != 0) return;
    float g[F];
#pragma unroll
    for (int j = 0; j < F; j++) g[j] = g_gmax[j];
    float lg[5];
#pragma unroll
    for (int c = 0; c < 5; c++) lg[c] = fcb[c];
    for (int j = 0; j < F; j++) {
        float gj = g[j];
#pragma unroll
        for (int c = 0; c < 5; c++) lg[c] = fmaf(gj, fcW[j * 5 + c], lg[c]);
    }
    float m = lg[0];
#pragma unroll
    for (int c = 1; c < 5; c++) m = fmaxf(m, lg[c]);
    float s = 0.f;
#pragma unroll
    for (int c = 0; c < 5; c++) s += expf(lg[c] - m);
    float ls = logf(s) + m;
#pragma unroll
    for (int c = 0; c < 5; c++) out[c] = lg[c] - ls;
}

extern "C" void kernel_launch(void* const* d_in, const int* in_sizes, int n_in,
                              void* d_out, int out_size) {
    const float* x   = (const float*)d_in[0];
    const int*   ei  = (const int*)d_in[1];   // jnp "int64" is int32 (x64 disabled)
    const float* W1  = (const float*)d_in[2];
    const float* b1  = (const float*)d_in[3];
    const float* W2  = (const float*)d_in[4];
    const float* b2  = (const float*)d_in[5];
    const float* fcW = (const float*)d_in[6];
    const float* fcb = (const float*)d_in[7];

    int n = in_sizes[0] / 8;
    int E = in_sizes[1] / 2;
    const int* src = ei;
    const int* dst = ei + E;

    int nb = (n + 255) / 256;
    int eb = (E + 255) / 256;
    int gb = (n * 32 + 255) / 256;   // one warp per node

    k_zero <<<nb, 256>>>(n);
    k_count<<<eb, 256>>>(dst, E);
    k_scan <<<1, SCAN_T>>>(n);
    k_fill <<<eb, 256>>>(src, dst, E);
    k_h1   <<<nb, 256>>>(x, W1, n);
    k_gather<<<gb, 256>>>(n);
    k_h2   <<<nb, 256>>>(W2, b1, n);
    k_gather<<<gb, 256>>>(n);
    k_final<<<nb, 256>>>(b2, n);
    k_head <<<1, 32>>>(fcW, fcb, (float*)d_out);
}